// round 1
// baseline (speedup 1.0000x reference)
#include <cuda_runtime.h>
#include <cuda_bf16.h>

// Net1: per (site,year) pair:
//   h_k = elu(Wh[k,0]*sx + Wh[k,1]*sy + bh[k]), k<64
//   psi = sigmoid(dot(h, Wpsi) + bpsi)                      -> out[0 .. 2M)
//   l   = dot(h, Wp[:64]) + bp
//   p_o = sigmoid(l + oxy_o * Wp[64]), o<2                  -> out[2M .. 6M)
//
// Inputs (metadata order): sxy, oxy, p(unused), W_h, b_h, W_psi, b_psi, W_p, b_p

#define NSITES 100000
#define NYEARS 20
#define NPAIRS (NSITES * NYEARS)   // 2,000,000
#define HD 64

__global__ __launch_bounds__(256, 8) void net1_kernel(
    const float* __restrict__ sxy,
    const float* __restrict__ oxy,
    const float* __restrict__ W_h,
    const float* __restrict__ b_h,
    const float* __restrict__ W_psi,
    const float* __restrict__ b_psi,
    const float* __restrict__ W_p,
    const float* __restrict__ b_p,
    float* __restrict__ out)
{
    // Per-k packed weights: {Wh0, Wh1, bh, Wpsi} + Wp
    __shared__ float4 s_w4[HD];
    __shared__ float  s_wp[HD];

    const int t = threadIdx.x;
    if (t < HD) {
        s_w4[t] = make_float4(W_h[2 * t], W_h[2 * t + 1], b_h[t], W_psi[t]);
        s_wp[t] = W_p[t];
    }
    __syncthreads();

    const int pair = blockIdx.x * blockDim.x + t;
    if (pair >= NPAIRS) return;

    const float2 s = __ldg((const float2*)sxy + pair);
    const float2 o = __ldg((const float2*)oxy + pair);
    const float wx   = __ldg(W_p + HD);
    const float bpsi = __ldg(b_psi);
    const float bp   = __ldg(b_p);

    float acc_psi = 0.0f;
    float acc_p   = 0.0f;

#pragma unroll 8
    for (int k = 0; k < HD; ++k) {
        const float4 w = s_w4[k];
        const float  z = fmaf(w.x, s.x, fmaf(w.y, s.y, w.z));
        // elu: z>0 ? z : exp(z)-1   (fast exp2-based exp; abs err ~1e-7, fine vs 1e-3)
        const float e = __expf(z) - 1.0f;
        const float h = (z > 0.0f) ? z : e;
        acc_psi = fmaf(h, w.w,     acc_psi);
        acc_p   = fmaf(h, s_wp[k], acc_p);
    }

    const float psi = __fdividef(1.0f, 1.0f + __expf(-(acc_psi + bpsi)));
    const float l   = acc_p + bp;
    const float p0  = __fdividef(1.0f, 1.0f + __expf(-fmaf(o.x, wx, l)));
    const float p1  = __fdividef(1.0f, 1.0f + __expf(-fmaf(o.y, wx, l)));

    out[pair] = psi;                               // psi block: 2M floats
    ((float2*)(out + NPAIRS))[pair] = make_float2(p0, p1);  // p block: 4M floats
}

extern "C" void kernel_launch(void* const* d_in, const int* in_sizes, int n_in,
                              void* d_out, int out_size) {
    const float* sxy   = (const float*)d_in[0];
    const float* oxy   = (const float*)d_in[1];
    // d_in[2] is p (zeros) — unused by the reference computation
    const float* W_h   = (const float*)d_in[3];
    const float* b_h   = (const float*)d_in[4];
    const float* W_psi = (const float*)d_in[5];
    const float* b_psi = (const float*)d_in[6];
    const float* W_p   = (const float*)d_in[7];
    const float* b_p   = (const float*)d_in[8];
    float* out = (float*)d_out;

    const int threads = 256;
    const int blocks  = (NPAIRS + threads - 1) / threads;
    net1_kernel<<<blocks, threads>>>(sxy, oxy, W_h, b_h, W_psi, b_psi, W_p, b_p, out);
}

// round 2
// speedup vs baseline: 1.2296x; 1.2296x over previous
#include <cuda_runtime.h>
#include <cuda_bf16.h>

// Net1: per (site,year) pair:
//   h_k = elu(Wh[k,0]*sx + Wh[k,1]*sy + bh[k]), k<64
//   psi = sigmoid(dot(h, Wpsi) + bpsi)                      -> out[0 .. 2M)
//   l   = dot(h, Wp[:64]) + bp
//   p_o = sigmoid(l + oxy_o * Wp[64]), o<2                  -> out[2M .. 6M)
//
// Round-2 scheme: 2 pairs/thread, packed f32x2 FMA (PTX-only instruction),
// weights pre-scaled by log2e and pre-duplicated in smem.
// elu identity: elu(z) = max(z,0) + min(exp(z)-1, 0)
//   with z2 = z*log2e:  elu = fma(ln2, max(z2,0), min(ex2(z2)-1, 0))

#define NSITES 100000
#define NYEARS 20
#define NPAIRS (NSITES * NYEARS)   // 2,000,000
#define HD 64
#define LOG2E 1.4426950408889634f
#define LN2   0.6931471805599453f

__device__ __forceinline__ float2 ffma2(float2 a, float2 b, float2 c) {
    float2 d;
    asm("fma.rn.f32x2 %0, %1, %2, %3;"
        : "=l"(*reinterpret_cast<unsigned long long*>(&d))
        : "l"(*reinterpret_cast<const unsigned long long*>(&a)),
          "l"(*reinterpret_cast<const unsigned long long*>(&b)),
          "l"(*reinterpret_cast<const unsigned long long*>(&c)));
    return d;
}

__device__ __forceinline__ float2 fadd2(float2 a, float2 b) {
    float2 d;
    asm("add.rn.f32x2 %0, %1, %2;"
        : "=l"(*reinterpret_cast<unsigned long long*>(&d))
        : "l"(*reinterpret_cast<const unsigned long long*>(&a)),
          "l"(*reinterpret_cast<const unsigned long long*>(&b)));
    return d;
}

__device__ __forceinline__ float ex2f(float x) {
    float r;
    asm("ex2.approx.ftz.f32 %0, %1;" : "=f"(r) : "f"(x));
    return r;
}

__device__ __forceinline__ float sigmoidf(float x) {
    return __fdividef(1.0f, 1.0f + __expf(-x));
}

__global__ __launch_bounds__(256) void net1_kernel(
    const float* __restrict__ sxy,
    const float* __restrict__ oxy,
    const float* __restrict__ W_h,
    const float* __restrict__ b_h,
    const float* __restrict__ W_psi,
    const float* __restrict__ b_psi,
    const float* __restrict__ W_p,
    const float* __restrict__ b_p,
    float* __restrict__ out)
{
    // Packed, pre-duplicated weights:
    //   s_wa[k] = {wx', wx', wy', wy'}   (wx' = Wh[k,0]*log2e, etc.)
    //   s_wb[k] = {bh', bh', wpsi, wpsi}
    //   s_wc[k] = {wp, wp}
    __shared__ float4 s_wa[HD];
    __shared__ float4 s_wb[HD];
    __shared__ float2 s_wc[HD];

    const int t = threadIdx.x;
    if (t < HD) {
        const float wx = W_h[2 * t]     * LOG2E;
        const float wy = W_h[2 * t + 1] * LOG2E;
        const float bh = b_h[t]         * LOG2E;
        const float wpsi = W_psi[t];
        s_wa[t] = make_float4(wx, wx, wy, wy);
        s_wb[t] = make_float4(bh, bh, wpsi, wpsi);
        s_wc[t] = make_float2(W_p[t], W_p[t]);
    }
    __syncthreads();

    const int gid = blockIdx.x * blockDim.x + t;   // handles pairs 2*gid, 2*gid+1
    const int base = gid * 2;
    if (base >= NPAIRS) return;

    // s4 = {sxa, sya, sxb, syb}; o4 = {oxa, oya, oxb, oyb}
    const float4 s4 = __ldg((const float4*)sxy + gid);
    const float4 o4 = __ldg((const float4*)oxy + gid);
    const float wx_p = __ldg(W_p + HD);
    const float bpsi = __ldg(b_psi);
    const float bp   = __ldg(b_p);

    const float2 sx2 = make_float2(s4.x, s4.z);   // x coords of the two pairs
    const float2 sy2 = make_float2(s4.y, s4.w);   // y coords
    const float2 ln2_2  = make_float2(LN2, LN2);
    const float2 neg1_2 = make_float2(-1.0f, -1.0f);

    float2 accpsi = make_float2(0.0f, 0.0f);
    float2 accp   = make_float2(0.0f, 0.0f);

#pragma unroll 8
    for (int k = 0; k < HD; ++k) {
        const float4 wa = s_wa[k];
        const float4 wb = s_wb[k];
        const float2 wp2 = s_wc[k];
        const float2 wx2   = make_float2(wa.x, wa.y);
        const float2 wy2   = make_float2(wa.z, wa.w);
        const float2 bh2   = make_float2(wb.x, wb.y);
        const float2 wpsi2 = make_float2(wb.z, wb.w);

        // z2 = log2e * (Wh·s + bh), packed over the 2 pairs
        const float2 z2 = ffma2(wx2, sx2, ffma2(wy2, sy2, bh2));

        // elu = fma(ln2, max(z2,0), min(ex2(z2)-1, 0))
        float2 e2;
        e2.x = ex2f(z2.x);
        e2.y = ex2f(z2.y);
        const float2 em1 = fadd2(e2, neg1_2);

        float2 mx, mn;
        mx.x = fmaxf(z2.x, 0.0f);
        mx.y = fmaxf(z2.y, 0.0f);
        mn.x = fminf(em1.x, 0.0f);
        mn.y = fminf(em1.y, 0.0f);
        const float2 h2 = ffma2(ln2_2, mx, mn);

        accpsi = ffma2(h2, wpsi2, accpsi);
        accp   = ffma2(h2, wp2,   accp);
    }

    // Epilogue (scalar per pair)
    const float psi_a = sigmoidf(accpsi.x + bpsi);
    const float psi_b = sigmoidf(accpsi.y + bpsi);
    const float la = accp.x + bp;
    const float lb = accp.y + bp;
    const float p0a = sigmoidf(fmaf(o4.x, wx_p, la));
    const float p1a = sigmoidf(fmaf(o4.y, wx_p, la));
    const float p0b = sigmoidf(fmaf(o4.z, wx_p, lb));
    const float p1b = sigmoidf(fmaf(o4.w, wx_p, lb));

    ((float2*)out)[gid] = make_float2(psi_a, psi_b);                 // psi block
    ((float4*)(out + NPAIRS))[gid] = make_float4(p0a, p1a, p0b, p1b); // p block

}

extern "C" void kernel_launch(void* const* d_in, const int* in_sizes, int n_in,
                              void* d_out, int out_size) {
    const float* sxy   = (const float*)d_in[0];
    const float* oxy   = (const float*)d_in[1];
    // d_in[2] is p (zeros) — unused by the reference computation
    const float* W_h   = (const float*)d_in[3];
    const float* b_h   = (const float*)d_in[4];
    const float* W_psi = (const float*)d_in[5];
    const float* b_psi = (const float*)d_in[6];
    const float* W_p   = (const float*)d_in[7];
    const float* b_p   = (const float*)d_in[8];
    float* out = (float*)d_out;

    const int threads = 256;
    const int nthreads_total = NPAIRS / 2;             // 2 pairs per thread
    const int blocks = (nthreads_total + threads - 1) / threads;
    net1_kernel<<<blocks, threads>>>(sxy, oxy, W_h, b_h, W_psi, b_psi, W_p, b_p, out);
}

// round 3
// speedup vs baseline: 1.4364x; 1.1682x over previous
#include <cuda_runtime.h>
#include <cuda_bf16.h>

// Net1 — Round 3: f32x2 lanes packed over (k,k+1) so weights load from smem
// UNduplicated; 4 pairs/thread amortize 3 LDS per 2-k group across 4 pairs.
// elu+1 identity:  elu(z)+1 = ln2*max(z2,0) + min(ex2(z2),1),  z2 = z*log2e
// Accumulate (h+1)·w, correct with precomputed sum(w) folded into biases.

#define NSITES 100000
#define NYEARS 20
#define NPAIRS (NSITES * NYEARS)   // 2,000,000
#define HD 64
#define NGRP (HD / 2)              // 32 groups of 2 hidden units
#define LOG2E 1.4426950408889634f
#define LN2   0.6931471805599453f

__device__ __forceinline__ float2 ffma2(float2 a, float2 b, float2 c) {
    float2 d;
    asm("fma.rn.f32x2 %0, %1, %2, %3;"
        : "=l"(*reinterpret_cast<unsigned long long*>(&d))
        : "l"(*reinterpret_cast<const unsigned long long*>(&a)),
          "l"(*reinterpret_cast<const unsigned long long*>(&b)),
          "l"(*reinterpret_cast<const unsigned long long*>(&c)));
    return d;
}

__device__ __forceinline__ float ex2f(float x) {
    float r;
    asm("ex2.approx.ftz.f32 %0, %1;" : "=f"(r) : "f"(x));
    return r;
}

__device__ __forceinline__ float sigmoidf(float x) {
    return __fdividef(1.0f, 1.0f + __expf(-x));
}

__global__ __launch_bounds__(128) void net1_kernel(
    const float* __restrict__ sxy,
    const float* __restrict__ oxy,
    const float* __restrict__ W_h,
    const float* __restrict__ b_h,
    const float* __restrict__ W_psi,
    const float* __restrict__ b_psi,
    const float* __restrict__ W_p,
    const float* __restrict__ b_p,
    float* __restrict__ out)
{
    // Per 2-k group (k0=2g, k1=2g+1), NO duplication:
    //   s_a[g] = {wx_k0, wx_k1, wy_k0, wy_k1} * log2e
    //   s_b[g] = {bh_k0*log2e, bh_k1*log2e, wpsi_k0, wpsi_k1}
    //   s_c[g] = {wp_k0, wp_k1}
    __shared__ float4 s_a[NGRP];
    __shared__ float4 s_b[NGRP];
    __shared__ float2 s_c[NGRP];
    __shared__ float  s_sums[2];   // {sum(W_psi), sum(W_p[:64])}

    const int t = threadIdx.x;
    if (t < NGRP) {
        const int k0 = 2 * t, k1 = 2 * t + 1;
        s_a[t] = make_float4(W_h[2 * k0] * LOG2E, W_h[2 * k1] * LOG2E,
                             W_h[2 * k0 + 1] * LOG2E, W_h[2 * k1 + 1] * LOG2E);
        s_b[t] = make_float4(b_h[k0] * LOG2E, b_h[k1] * LOG2E,
                             W_psi[k0], W_psi[k1]);
        s_c[t] = make_float2(W_p[k0], W_p[k1]);
    }
    if (t == 0) {
        float s1 = 0.0f, s2 = 0.0f;
#pragma unroll
        for (int k = 0; k < HD; ++k) { s1 += W_psi[k]; s2 += W_p[k]; }
        s_sums[0] = s1; s_sums[1] = s2;
    }
    __syncthreads();

    const int gid  = blockIdx.x * blockDim.x + t;   // handles pairs 4*gid..4*gid+3
    const int base = gid * 4;
    if (base >= NPAIRS) return;

    const float4 sA = __ldg((const float4*)sxy + 2 * gid);      // {sx0,sy0,sx1,sy1}
    const float4 sB = __ldg((const float4*)sxy + 2 * gid + 1);  // {sx2,sy2,sx3,sy3}
    const float4 oA = __ldg((const float4*)oxy + 2 * gid);
    const float4 oB = __ldg((const float4*)oxy + 2 * gid + 1);
    const float wx_p = __ldg(W_p + HD);
    const float bpsi_eff = __ldg(b_psi) - s_sums[0];   // fold -sum(wpsi)
    const float bp_eff   = __ldg(b_p)   - s_sums[1];   // fold -sum(wp)

    // Loop-invariant duplicated inputs (register pairs, built once)
    const float2 sx[4] = { make_float2(sA.x, sA.x), make_float2(sA.z, sA.z),
                           make_float2(sB.x, sB.x), make_float2(sB.z, sB.z) };
    const float2 sy[4] = { make_float2(sA.y, sA.y), make_float2(sA.w, sA.w),
                           make_float2(sB.y, sB.y), make_float2(sB.w, sB.w) };
    const float2 ln2_2 = make_float2(LN2, LN2);

    float2 apsi[4], ap[4];
#pragma unroll
    for (int p = 0; p < 4; ++p) {
        apsi[p] = make_float2(0.0f, 0.0f);
        ap[p]   = make_float2(0.0f, 0.0f);
    }

#pragma unroll 8
    for (int g = 0; g < NGRP; ++g) {
        const float4 a = s_a[g];
        const float4 b = s_b[g];
        const float2 wp2 = s_c[g];
        const float2 wx2   = make_float2(a.x, a.y);
        const float2 wy2   = make_float2(a.z, a.w);
        const float2 bh2   = make_float2(b.x, b.y);
        const float2 wpsi2 = make_float2(b.z, b.w);

#pragma unroll
        for (int p = 0; p < 4; ++p) {
            // z2 = log2e * (Wh·s + bh), packed over the 2 hidden units
            const float2 z2 = ffma2(wx2, sx[p], ffma2(wy2, sy[p], bh2));
            float2 mn, mx;
            mn.x = fminf(ex2f(z2.x), 1.0f);
            mn.y = fminf(ex2f(z2.y), 1.0f);
            mx.x = fmaxf(z2.x, 0.0f);
            mx.y = fmaxf(z2.y, 0.0f);
            const float2 h1 = ffma2(ln2_2, mx, mn);   // elu(z) + 1
            apsi[p] = ffma2(h1, wpsi2, apsi[p]);
            ap[p]   = ffma2(h1, wp2,   ap[p]);
        }
    }

    // Epilogue
    float psi_v[4], p_v[4][2];
    const float ox[4] = { oA.x, oA.z, oB.x, oB.z };
    const float oy[4] = { oA.y, oA.w, oB.y, oB.w };
#pragma unroll
    for (int p = 0; p < 4; ++p) {
        psi_v[p] = sigmoidf(apsi[p].x + apsi[p].y + bpsi_eff);
        const float l = ap[p].x + ap[p].y + bp_eff;
        p_v[p][0] = sigmoidf(fmaf(ox[p], wx_p, l));
        p_v[p][1] = sigmoidf(fmaf(oy[p], wx_p, l));
    }

    ((float4*)out)[gid] = make_float4(psi_v[0], psi_v[1], psi_v[2], psi_v[3]);
    float4* pout = (float4*)(out + NPAIRS);
    pout[2 * gid]     = make_float4(p_v[0][0], p_v[0][1], p_v[1][0], p_v[1][1]);
    pout[2 * gid + 1] = make_float4(p_v[2][0], p_v[2][1], p_v[3][0], p_v[3][1]);
}

extern "C" void kernel_launch(void* const* d_in, const int* in_sizes, int n_in,
                              void* d_out, int out_size) {
    const float* sxy   = (const float*)d_in[0];
    const float* oxy   = (const float*)d_in[1];
    // d_in[2] is p (zeros) — unused by the reference computation
    const float* W_h   = (const float*)d_in[3];
    const float* b_h   = (const float*)d_in[4];
    const float* W_psi = (const float*)d_in[5];
    const float* b_psi = (const float*)d_in[6];
    const float* W_p   = (const float*)d_in[7];
    const float* b_p   = (const float*)d_in[8];
    float* out = (float*)d_out;

    const int threads = 128;
    const int nthreads_total = NPAIRS / 4;             // 4 pairs per thread
    const int blocks = (nthreads_total + threads - 1) / threads;
    net1_kernel<<<blocks, threads>>>(sxy, oxy, W_h, b_h, W_psi, b_psi, W_p, b_p, out);
}